// round 14
// baseline (speedup 1.0000x reference)
#include <cuda_runtime.h>
#include <math.h>

#define NB   128
#define NG   360
#define NGI  174
#define NEF  512
#define NET  512
#define NU   512
#define NAU  32
#define NVOC 5000
#define NT   20
#define NKS  1024               // serial gates K: [ctx | a]
#define N4U  (4 * NU)           // 2048
#define NSK  8                  // split-K factor for serial gates GEMM
#define NKSP (NKS / NSK)        // 128

typedef unsigned long long ull;

// ---------------- scratch (device globals; no allocation allowed) ----------------
__device__ float g_feat[(size_t)NB * NG * NEF];
__device__ float g_f1[(size_t)NB * NG * NAU];
__device__ float g_aseq[(size_t)(NT + 1) * NB * NU];
__device__ float g_c[NB * NU];
__device__ float g_xfull[NB * NKS];
__device__ float g_gpart[(size_t)NSK * NB * N4U];
__device__ float g_Wcat[(size_t)N4U * NKS];
__device__ float g_bsum[N4U];
__device__ float g_embseq[(size_t)NT * NB * NET];
__device__ float g_embg[(size_t)NT * NB * N4U];
__device__ float g_d1big[(size_t)NT * NB * 256];
__device__ float g_lgbig[(size_t)NT * NB * NVOC];

// ---------------- helpers ----------------
__device__ __forceinline__ float warpSum(float v) {
    #pragma unroll
    for (int o = 16; o; o >>= 1) v += __shfl_xor_sync(0xffffffffu, v, o);
    return v;
}
__device__ __forceinline__ float warpMax(float v) {
    #pragma unroll
    for (int o = 16; o; o >>= 1) v = fmaxf(v, __shfl_xor_sync(0xffffffffu, v, o));
    return v;
}
__device__ __forceinline__ float blockSum(float v, float* sm) {
    __syncthreads();
    int lane = threadIdx.x & 31, wid = threadIdx.x >> 5;
    v = warpSum(v);
    if (lane == 0) sm[wid] = v;
    __syncthreads();
    int nw = blockDim.x >> 5;
    float r = (threadIdx.x < nw) ? sm[threadIdx.x] : 0.f;
    if (wid == 0) { r = warpSum(r); if (lane == 0) sm[0] = r; }
    __syncthreads();
    return sm[0];
}
__device__ __forceinline__ float blockMax(float v, float* sm) {
    __syncthreads();
    int lane = threadIdx.x & 31, wid = threadIdx.x >> 5;
    v = warpMax(v);
    if (lane == 0) sm[wid] = v;
    __syncthreads();
    int nw = blockDim.x >> 5;
    float r = (threadIdx.x < nw) ? sm[threadIdx.x] : -INFINITY;
    if (wid == 0) { r = warpMax(r); if (lane == 0) sm[0] = r; }
    __syncthreads();
    return sm[0];
}
__device__ __forceinline__ float sigmoidf(float x) { return 1.f / (1.f + expf(-x)); }
__device__ __forceinline__ float leakyf(float x)  { return x >= 0.f ? x : 0.2f * x; }

// packed dual-fp32 FMA — exact fp32 per lane; only reachable via PTX (ptxas won't emit)
__device__ __forceinline__ void ffma2(ull& d, ull a, ull b) {
    asm("fma.rn.f32x2 %0, %1, %2, %0;" : "+l"(d) : "l"(a), "l"(b));
}
__device__ __forceinline__ void unpack2(float& lo, float& hi, ull v) {
    asm("mov.b64 {%0, %1}, %2;" : "=f"(lo), "=f"(hi) : "l"(v));
}

// =================== 128x128-tile SGEMM, 8x8 microtile via FFMA2, K-chunk 8 ==========
// Accumulators pair along m (A m-contiguous in smem -> direct 8B pair loads);
// B stored DUPLICATED in smem ((b,b) at float offset 2*col) so b-operands are
// direct pair loads. Per k: 6 LDS.128 + 32 FFMA2 (vs 4 LDS + 64 FFMA scalar).
// Requires M % 128 == 0 (all call sites). EXACT=true: N%128==0, K%8==0 -> no guards.
template<bool BT, int EPI, bool EXACT>
__global__ void __launch_bounds__(256, 2) gemm128_kernel(
    const float* __restrict__ A, int lda, size_t aBatch,
    const float* __restrict__ Bm, int ldb, size_t bBatch,
    const float* __restrict__ bias, size_t biasBatch,
    float* __restrict__ C, int ldc, size_t cBatch,
    int M, int N, int K)
{
    __shared__ __align__(16) float As[2][8][132];
    __shared__ __align__(16) float Bs[2][8][264];   // dup: 256 used + 8 pad
    A    += (size_t)blockIdx.z * aBatch;
    Bm   += (size_t)blockIdx.z * bBatch;
    if (bias) bias += (size_t)blockIdx.z * biasBatch;
    C    += (size_t)blockIdx.z * cBatch;

    const int n0 = blockIdx.x * 128;
    const int m0 = blockIdx.y * 128;
    const int tid = threadIdx.x;
    const int tx = tid & 15;
    const int ty = tid >> 4;

    // A staging: row amr (0..127), k base akb (0 or 4)
    const int amr = tid >> 1;
    const int akb = (tid & 1) << 2;
    const float* aPtr = A + (size_t)(m0 + amr) * lda + akb;
    // B staging BT=true: row bnr (0..127), k base bkb (0 or 4)
    const int bnr = tid >> 1;
    const int bkb = (tid & 1) << 2;
    // B staging BT=false: k row bkr (0..7), n base bnc (0..124 step 4)
    const int bkr = tid >> 5;
    const int bnc = (tid & 31) << 2;
    const float* bPtr = BT ? (Bm + (size_t)(n0 + bnr) * ldb + bkb)
                           : (Bm + (size_t)bkr * ldb + n0 + bnc);
    const bool bok = EXACT || (BT ? (n0 + bnr) < N : (n0 + bnc + 4) <= N);

    ull acc2[4][8] = {};          // acc2[mp][j]: rows m0+ty*8+2mp(+1), col j of 8
    float aR[4], bR[4];
    const float4 z4 = make_float4(0.f, 0.f, 0.f, 0.f);
    const int nch = (K + 7) >> 3;

    // ---- prologue: chunk 0 ----
    if (EXACT) {
        float4 v = *(const float4*)aPtr;
        aR[0] = v.x; aR[1] = v.y; aR[2] = v.z; aR[3] = v.w;
    } else {
        #pragma unroll
        for (int j = 0; j < 4; j++) aR[j] = (akb + j < K) ? aPtr[j] : 0.f;
    }
    aPtr += 8;
    if (BT) {
        float4 v = (bok && (EXACT || bkb + 4 <= K)) ? *(const float4*)bPtr : z4;
        bR[0] = v.x; bR[1] = v.y; bR[2] = v.z; bR[3] = v.w;
        bPtr += 8;
    } else {
        float4 v = (bok && (EXACT || bkr < K)) ? *(const float4*)bPtr : z4;
        bR[0] = v.x; bR[1] = v.y; bR[2] = v.z; bR[3] = v.w;
        bPtr += (size_t)8 * ldb;
    }
    #pragma unroll
    for (int j = 0; j < 4; j++) As[0][akb + j][amr] = aR[j];
    if (BT) {
        #pragma unroll
        for (int j = 0; j < 4; j++)
            *(float2*)&Bs[0][bkb + j][2 * bnr] = make_float2(bR[j], bR[j]);
    } else {
        #pragma unroll
        for (int j = 0; j < 4; j++)
            *(float2*)&Bs[0][bkr][2 * (bnc + j)] = make_float2(bR[j], bR[j]);
    }
    __syncthreads();

    for (int kc = 0; kc < nch; kc++) {
        const int cur = kc & 1, nxt = cur ^ 1;
        const bool more = (kc + 1) < nch;
        if (more) {
            const int k0 = (kc + 1) << 3;
            if (EXACT) {
                float4 v = *(const float4*)aPtr;
                aR[0] = v.x; aR[1] = v.y; aR[2] = v.z; aR[3] = v.w;
            } else {
                #pragma unroll
                for (int j = 0; j < 4; j++) aR[j] = (k0 + akb + j < K) ? aPtr[j] : 0.f;
            }
            aPtr += 8;
            if (BT) {
                float4 v = (bok && (EXACT || k0 + bkb + 4 <= K)) ? *(const float4*)bPtr : z4;
                bR[0] = v.x; bR[1] = v.y; bR[2] = v.z; bR[3] = v.w;
                bPtr += 8;
            } else {
                float4 v = (bok && (EXACT || k0 + bkr < K)) ? *(const float4*)bPtr : z4;
                bR[0] = v.x; bR[1] = v.y; bR[2] = v.z; bR[3] = v.w;
                bPtr += (size_t)8 * ldb;
            }
        }
        #pragma unroll
        for (int k = 0; k < 8; k++) {
            ulonglong2 a01 = *(const ulonglong2*)&As[cur][k][ty << 3];
            ulonglong2 a23 = *(const ulonglong2*)&As[cur][k][(ty << 3) + 4];
            ulonglong2 b01 = *(const ulonglong2*)&Bs[cur][k][tx << 3];
            ulonglong2 b23 = *(const ulonglong2*)&Bs[cur][k][(tx << 3) + 4];
            ulonglong2 b45 = *(const ulonglong2*)&Bs[cur][k][128 + (tx << 3)];
            ulonglong2 b67 = *(const ulonglong2*)&Bs[cur][k][128 + (tx << 3) + 4];
            ull ap[4] = {a01.x, a01.y, a23.x, a23.y};
            ull bp[8] = {b01.x, b01.y, b23.x, b23.y, b45.x, b45.y, b67.x, b67.y};
            #pragma unroll
            for (int mp = 0; mp < 4; mp++) {
                #pragma unroll
                for (int j = 0; j < 8; j++) ffma2(acc2[mp][j], ap[mp], bp[j]);
            }
        }
        if (more) {
            #pragma unroll
            for (int j = 0; j < 4; j++) As[nxt][akb + j][amr] = aR[j];
            if (BT) {
                #pragma unroll
                for (int j = 0; j < 4; j++)
                    *(float2*)&Bs[nxt][bkb + j][2 * bnr] = make_float2(bR[j], bR[j]);
            } else {
                #pragma unroll
                for (int j = 0; j < 4; j++)
                    *(float2*)&Bs[nxt][bkr][2 * (bnc + j)] = make_float2(bR[j], bR[j]);
            }
            __syncthreads();
        }
    }

    // ---- epilogue: two 4-col groups; N % 4 == 0 at all call sites ----
    #pragma unroll
    for (int gEp = 0; gEp < 2; gEp++) {
        const int c = n0 + gEp * 64 + (tx << 2);
        const int jb = gEp * 4;
        if (EXACT || c + 4 <= N) {
            float bv0 = bias ? bias[c]     : 0.f;
            float bv1 = bias ? bias[c + 1] : 0.f;
            float bv2 = bias ? bias[c + 2] : 0.f;
            float bv3 = bias ? bias[c + 3] : 0.f;
            #pragma unroll
            for (int mp = 0; mp < 4; mp++) {
                float lo0, hi0, lo1, hi1, lo2, hi2, lo3, hi3;
                unpack2(lo0, hi0, acc2[mp][jb]);
                unpack2(lo1, hi1, acc2[mp][jb + 1]);
                unpack2(lo2, hi2, acc2[mp][jb + 2]);
                unpack2(lo3, hi3, acc2[mp][jb + 3]);
                int m = m0 + (ty << 3) + 2 * mp;
                float v0 = lo0 + bv0, v1 = lo1 + bv1, v2 = lo2 + bv2, v3 = lo3 + bv3;
                float w0 = hi0 + bv0, w1 = hi1 + bv1, w2 = hi2 + bv2, w3 = hi3 + bv3;
                if (EPI == 1) {
                    v0 = leakyf(v0); v1 = leakyf(v1); v2 = leakyf(v2); v3 = leakyf(v3);
                    w0 = leakyf(w0); w1 = leakyf(w1); w2 = leakyf(w2); w3 = leakyf(w3);
                }
                if (EPI == 2) {
                    v0 = fmaxf(v0, 0.f); v1 = fmaxf(v1, 0.f); v2 = fmaxf(v2, 0.f); v3 = fmaxf(v3, 0.f);
                    w0 = fmaxf(w0, 0.f); w1 = fmaxf(w1, 0.f); w2 = fmaxf(w2, 0.f); w3 = fmaxf(w3, 0.f);
                }
                *(float4*)&C[(size_t)m * ldc + c]       = make_float4(v0, v1, v2, v3);
                *(float4*)&C[(size_t)(m + 1) * ldc + c] = make_float4(w0, w1, w2, w3);
            }
        }
    }
}

// ---------------- 64x64-tile SGEMM — used for f1 (N=32) only -------------
template<bool BT, int EPI>
__global__ void __launch_bounds__(256) gemm64_kernel(
    const float* __restrict__ A, int lda, size_t aBatch,
    const float* __restrict__ Bm, int ldb, size_t bBatch,
    const float* __restrict__ bias, size_t biasBatch,
    float* __restrict__ C, int ldc, size_t cBatch,
    int M, int N, int K)
{
    __shared__ __align__(16) float As[2][16][68];
    __shared__ __align__(16) float Bs[2][16][68];
    A    += (size_t)blockIdx.z * aBatch;
    Bm   += (size_t)blockIdx.z * bBatch;
    if (bias) bias += (size_t)blockIdx.z * biasBatch;
    C    += (size_t)blockIdx.z * cBatch;

    const int n0 = blockIdx.x * 64;
    const int m0 = blockIdx.y * 64;
    const int tid = threadIdx.x;
    const int tx = tid & 15;
    const int ty = tid >> 4;
    const int am = tid >> 2;
    const int ak = (tid & 3) << 2;
    const int bkf = tid >> 4;
    const int bnf = (tid & 15) << 2;
    const int bnr = tid >> 2;
    const int bkr = (tid & 3) << 2;

    float acc[4][4] = {};
    float aR[4], bR[4];
    const int nch = (K + 15) >> 4;
    const bool mok = (m0 + am) < M;

    #pragma unroll
    for (int j = 0; j < 4; j++) {
        int k = ak + j;
        aR[j] = (mok && k < K) ? A[(size_t)(m0 + am) * lda + k] : 0.f;
    }
    if (BT) {
        #pragma unroll
        for (int j = 0; j < 4; j++) {
            int k = bkr + j;
            bR[j] = ((n0 + bnr) < N && k < K) ? Bm[(size_t)(n0 + bnr) * ldb + k] : 0.f;
        }
    } else {
        #pragma unroll
        for (int j = 0; j < 4; j++) {
            int n = n0 + bnf + j;
            bR[j] = (n < N && bkf < K) ? Bm[(size_t)bkf * ldb + n] : 0.f;
        }
    }
    #pragma unroll
    for (int j = 0; j < 4; j++) As[0][ak + j][am] = aR[j];
    if (BT) {
        #pragma unroll
        for (int j = 0; j < 4; j++) Bs[0][bkr + j][bnr] = bR[j];
    } else {
        #pragma unroll
        for (int j = 0; j < 4; j++) Bs[0][bkf][bnf + j] = bR[j];
    }
    __syncthreads();

    for (int kc = 0; kc < nch; kc++) {
        const int cur = kc & 1, nxt = cur ^ 1;
        const bool more = (kc + 1) < nch;
        if (more) {
            const int k0 = (kc + 1) << 4;
            #pragma unroll
            for (int j = 0; j < 4; j++) {
                int k = k0 + ak + j;
                aR[j] = (mok && k < K) ? A[(size_t)(m0 + am) * lda + k] : 0.f;
            }
            if (BT) {
                #pragma unroll
                for (int j = 0; j < 4; j++) {
                    int k = k0 + bkr + j;
                    bR[j] = ((n0 + bnr) < N && k < K) ? Bm[(size_t)(n0 + bnr) * ldb + k] : 0.f;
                }
            } else {
                #pragma unroll
                for (int j = 0; j < 4; j++) {
                    int n = n0 + bnf + j;
                    int k = k0 + bkf;
                    bR[j] = (n < N && k < K) ? Bm[(size_t)k * ldb + n] : 0.f;
                }
            }
        }
        #pragma unroll
        for (int k = 0; k < 16; k++) {
            float4 a4 = *(const float4*)&As[cur][k][ty << 2];
            float4 b4 = *(const float4*)&Bs[cur][k][tx << 2];
            acc[0][0] += a4.x * b4.x; acc[0][1] += a4.x * b4.y;
            acc[0][2] += a4.x * b4.z; acc[0][3] += a4.x * b4.w;
            acc[1][0] += a4.y * b4.x; acc[1][1] += a4.y * b4.y;
            acc[1][2] += a4.y * b4.z; acc[1][3] += a4.y * b4.w;
            acc[2][0] += a4.z * b4.x; acc[2][1] += a4.z * b4.y;
            acc[2][2] += a4.z * b4.z; acc[2][3] += a4.z * b4.w;
            acc[3][0] += a4.w * b4.x; acc[3][1] += a4.w * b4.y;
            acc[3][2] += a4.w * b4.z; acc[3][3] += a4.w * b4.w;
        }
        if (more) {
            #pragma unroll
            for (int j = 0; j < 4; j++) As[nxt][ak + j][am] = aR[j];
            if (BT) {
                #pragma unroll
                for (int j = 0; j < 4; j++) Bs[nxt][bkr + j][bnr] = bR[j];
            } else {
                #pragma unroll
                for (int j = 0; j < 4; j++) Bs[nxt][bkf][bnf + j] = bR[j];
            }
            __syncthreads();
        }
    }

    #pragma unroll
    for (int i = 0; i < 4; i++) {
        int m = m0 + (ty << 2) + i;
        if (m < M) {
            #pragma unroll
            for (int j = 0; j < 4; j++) {
                int n = n0 + (tx << 2) + j;
                if (n < N) {
                    float v = acc[i][j] + (bias ? bias[n] : 0.f);
                    if (EPI == 1) v = leakyf(v);
                    if (EPI == 2) v = fmaxf(v, 0.f);
                    C[(size_t)m * ldc + n] = v;
                }
            }
        }
    }
}

// ---------------- LayerNorm over rows of length 512 (in-place) ----------------
__global__ void __launch_bounds__(128) ln_rows_kernel(float* __restrict__ X,
    const float* __restrict__ gg, const float* __restrict__ bb)
{
    __shared__ float red[32];
    size_t row = blockIdx.x;
    float* xr = X + row * NEF;
    int tid = threadIdx.x;
    float v[4];
    #pragma unroll
    for (int j = 0; j < 4; j++) v[j] = xr[tid + 128 * j];
    float s = v[0] + v[1] + v[2] + v[3];
    float mean = blockSum(s, red) * (1.f / NEF);
    float sq = 0.f;
    #pragma unroll
    for (int j = 0; j < 4; j++) { float d = v[j] - mean; sq += d * d; }
    float var = blockSum(sq, red) * (1.f / NEF);
    float r = rsqrtf(var + 1e-5f);
    #pragma unroll
    for (int j = 0; j < 4; j++) {
        int cidx = tid + 128 * j;
        xr[cidx] = (v[j] - mean) * r * gg[cidx] + bb[cidx];
    }
}

// ---------------- pack [W_ih[:, :512] | W_hh] and b_ih + b_hh ----------------
__global__ void pack_kernel(const float* __restrict__ W_ih, const float* __restrict__ W_hh,
                            const float* __restrict__ b_ih, const float* __restrict__ b_hh)
{
    size_t idx = (size_t)blockIdx.x * blockDim.x + threadIdx.x;
    if (idx < (size_t)N4U * NKS) {
        int j = (int)(idx / NKS), k = (int)(idx % NKS);
        g_Wcat[idx] = (k < NEF) ? W_ih[(size_t)j * (NEF + NET) + k]
                                : W_hh[(size_t)j * NU + (k - NEF)];
    }
    if (idx < N4U) g_bsum[idx] = b_ih[idx] + b_hh[idx];
}

__global__ void init_kernel(const float* __restrict__ a0, const float* __restrict__ c0)
{
    int idx = blockIdx.x * blockDim.x + threadIdx.x;
    if (idx < NB * NU) { g_aseq[idx] = a0[idx]; g_c[idx] = c0[idx]; }
}

// ---------------- gather embedding rows: embseq[r = t*NB + b] = emb[text[b][t]] ----------
__global__ void gather_emb_kernel(const float* __restrict__ emb, const int* __restrict__ text)
{
    size_t idx = (size_t)blockIdx.x * blockDim.x + threadIdx.x;
    if (idx >= (size_t)NT * NB * NET) return;
    int r = (int)(idx >> 9);        // NET = 512
    int col = (int)(idx & 511);
    int t = r / NB, b = r % NB;
    int tok = text[b * NT + t];
    g_embseq[idx] = emb[(size_t)tok * NET + col];
}

// ---------------- attention step: h2, scores, softmax, ctx, xin pack ----------------
__global__ void __launch_bounds__(512) attn_kernel(
    const float* __restrict__ f1, const float* __restrict__ feat,
    const float* __restrict__ a,
    const float* __restrict__ W2, const float* __restrict__ b2,
    const float* __restrict__ V, const float* __restrict__ bV,
    float* __restrict__ xfull, float* __restrict__ attn_out, int t)
{
    int b = blockIdx.x, chunk = blockIdx.y, tid = threadIdx.x;
    __shared__ float h2s[NAU];
    __shared__ float part[16][NAU];
    __shared__ float ss[NG];
    __shared__ float red[32];
    __shared__ float cpart[4][128];

    {
        int au = tid & 31, seg = tid >> 5;
        const float* arow = a + b * NU;
        float acc = 0.f;
        #pragma unroll 8
        for (int kk = 0; kk < 32; kk++) {
            int k = seg * 32 + kk;
            acc += arow[k] * W2[k * NAU + au];
        }
        part[seg][au] = acc;
    }
    __syncthreads();
    if (tid < NAU) {
        float s = 0.f;
        #pragma unroll
        for (int i = 0; i < 16; i++) s += part[i][tid];
        h2s[tid] = fmaxf(s + b2[tid], 0.f);
    }
    __syncthreads();

    int wid = tid >> 5, lane = tid & 31;
    for (int g = wid; g < NG; g += 16) {
        float v = tanhf(f1[((size_t)b * NG + g) * NAU + lane] + h2s[lane]) * V[lane];
        v = warpSum(v);
        if (lane == 0) ss[g] = v + bV[0];
    }
    __syncthreads();

    float mx = -INFINITY;
    for (int g = tid; g < NG; g += 512) mx = fmaxf(mx, ss[g]);
    mx = blockMax(mx, red);
    float sum = 0.f;
    for (int g = tid; g < NG; g += 512) { float e = expf(ss[g] - mx); ss[g] = e; sum += e; }
    sum = blockSum(sum, red);
    float inv = 1.f / sum;
    for (int g = tid; g < NG; g += 512) {
        float w = ss[g] * inv;
        ss[g] = w;
        if (chunk == 0 && attn_out) attn_out[((size_t)b * NT + t) * NG + g] = w;
    }
    if (chunk == 0)
        xfull[(size_t)b * NKS + NEF + tid] = a[b * NU + tid];
    __syncthreads();

    {
        int q = tid >> 7, e = tid & 127;
        int ef = chunk * 128 + e;
        const float* fb = feat + (size_t)b * NG * NEF + ef;
        float acc = 0.f;
        int g0 = q * 90;
        #pragma unroll 5
        for (int g = g0; g < g0 + 90; g++) acc += ss[g] * fb[(size_t)g * NEF];
        cpart[q][e] = acc;
    }
    __syncthreads();
    if (tid < 128) {
        float v = cpart[0][tid] + cpart[1][tid] + cpart[2][tid] + cpart[3][tid];
        xfull[(size_t)b * NKS + chunk * 128 + tid] = v;
    }
}

// ---------------- LSTM: split-K partials + embg(t) + pointwise + LN(leaky(h)) ---------
__global__ void __launch_bounds__(512) lstm_kernel(
    const float* __restrict__ gpart, const float* __restrict__ embg_t,
    float* __restrict__ aout, float* __restrict__ c,
    const float* __restrict__ lng, const float* __restrict__ lnb)
{
    __shared__ float red[32];
    int b = blockIdx.x, u = threadIdx.x;
    const float* er = embg_t + (size_t)b * N4U;
    float gi = er[u], gf = er[NU + u], gg = er[2 * NU + u], go = er[3 * NU + u];
    #pragma unroll
    for (int z = 0; z < NSK; z++) {
        const float* gr = gpart + (size_t)z * NB * N4U + (size_t)b * N4U;
        gi += gr[u]; gf += gr[NU + u]; gg += gr[2 * NU + u]; go += gr[3 * NU + u];
    }
    float cn = sigmoidf(gf) * c[b * NU + u] + sigmoidf(gi) * tanhf(gg);
    float h  = sigmoidf(go) * tanhf(cn);
    c[b * NU + u] = cn;
    float hl = leakyf(h);
    float mean = blockSum(hl, red) * (1.f / NU);
    float d = hl - mean;
    float var = blockSum(d * d, red) * (1.f / NU);
    float r = rsqrtf(var + 1e-5f);
    aout[b * NU + u] = d * r * lng[u] + lnb[u];
}

// ---------------- batched vocab softmax: rows r = t*NB + b -> out[b,t,:] ----------------
__global__ void __launch_bounds__(512) vsm_kernel(
    const float* __restrict__ logits, float* __restrict__ out)
{
    __shared__ float red[32];
    int r = blockIdx.x, tid = threadIdx.x;
    int t = r / NB, b = r % NB;
    const float* lr = logits + (size_t)r * NVOC;
    float* orow = out + ((size_t)b * NT + t) * NVOC;
    float mx = -INFINITY;
    for (int v = tid; v < NVOC; v += 512) mx = fmaxf(mx, lr[v]);
    mx = blockMax(mx, red);
    float s = 0.f;
    for (int v = tid; v < NVOC; v += 512) { float e = expf(lr[v] - mx); orow[v] = e; s += e; }
    s = blockSum(s, red);
    float inv = 1.f / s;
    for (int v = tid; v < NVOC; v += 512) orow[v] *= inv;
}

// ---------------- host ----------------
extern "C" void kernel_launch(void* const* d_in, const int* in_sizes, int n_in,
                              void* d_out, int out_size)
{
    const float* features = (const float*)d_in[0];
    const int*   text     = (const int*)  d_in[1];
    const float* a0       = (const float*)d_in[2];
    const float* c0       = (const float*)d_in[3];
    const float* enc_W    = (const float*)d_in[4];
    const float* enc_b    = (const float*)d_in[5];
    const float* enc_ln_g = (const float*)d_in[6];
    const float* enc_ln_b = (const float*)d_in[7];
    const float* attn_W1  = (const float*)d_in[8];
    const float* attn_b1  = (const float*)d_in[9];
    const float* attn_W2  = (const float*)d_in[10];
    const float* attn_b2  = (const float*)d_in[11];
    const float* attn_V   = (const float*)d_in[12];
    const float* attn_bV  = (const float*)d_in[13];
    const float* emb      = (const float*)d_in[14];
    const float* W_ih     = (const float*)d_in[15];
    const float* W_hh     = (const float*)d_in[16];
    const float* b_ih     = (const float*)d_in[17];
    const float* b_hh     = (const float*)d_in[18];
    const float* ln_g     = (const float*)d_in[19];
    const float* ln_b     = (const float*)d_in[20];
    const float* dec_W1   = (const float*)d_in[21];
    const float* dec_b1   = (const float*)d_in[22];
    const float* dec_W2   = (const float*)d_in[23];
    const float* dec_b2   = (const float*)d_in[24];

    float *p_feat, *p_f1, *p_aseq, *p_c, *p_x, *p_gp, *p_W, *p_bs, *p_es, *p_eg, *p_d1, *p_lg;
    cudaGetSymbolAddress((void**)&p_feat, g_feat);
    cudaGetSymbolAddress((void**)&p_f1,   g_f1);
    cudaGetSymbolAddress((void**)&p_aseq, g_aseq);
    cudaGetSymbolAddress((void**)&p_c,    g_c);
    cudaGetSymbolAddress((void**)&p_x,    g_xfull);
    cudaGetSymbolAddress((void**)&p_gp,   g_gpart);
    cudaGetSymbolAddress((void**)&p_W,    g_Wcat);
    cudaGetSymbolAddress((void**)&p_bs,   g_bsum);
    cudaGetSymbolAddress((void**)&p_es,   g_embseq);
    cudaGetSymbolAddress((void**)&p_eg,   g_embg);
    cudaGetSymbolAddress((void**)&p_d1,   g_d1big);
    cudaGetSymbolAddress((void**)&p_lg,   g_lgbig);

    float* out = (float*)d_out;
    float* attn_out = nullptr;
    long long need = (long long)NB * NT * NVOC + (long long)NB * NT * NG;
    if ((long long)out_size >= need) attn_out = out + (size_t)NB * NT * NVOC;

    pack_kernel<<<(int)(((size_t)N4U * NKS + 255) / 256), 256>>>(W_ih, W_hh, b_ih, b_hh);
    init_kernel<<<(NB * NU + 255) / 256, 256>>>(a0, c0);
    gather_emb_kernel<<<(int)(((size_t)NT * NB * NET + 255) / 256), 256>>>(emb, text);

    // embg = embseq @ W_ih[:, 512:1024]^T + (b_ih + b_hh): [2560 x 2048 x 512] (exact)
    {
        dim3 geg(N4U / 128, (NT * NB) / 128, 1);
        gemm128_kernel<true, 0, true><<<geg, 256>>>(
            p_es, NET, 0,
            W_ih + NEF, NEF + NET, 0,
            p_bs, 0,
            p_eg, N4U, 0,
            NT * NB, N4U, NET);
    }

    // encoder: per-group GEMM [128 x 512 x 174] + leaky, then LN (K guarded)
    {
        dim3 ge(NEF / 128, NB / 128, NG);
        gemm128_kernel<false, 1, false><<<ge, 256>>>(
            features, NG * NGI, (size_t)NGI,
            enc_W, NEF, (size_t)NGI * NEF,
            enc_b, (size_t)NEF,
            p_feat, NG * NEF, (size_t)NEF,
            NB, NEF, NGI);
        ln_rows_kernel<<<NB * NG, 128>>>(p_feat, enc_ln_g, enc_ln_b);
    }
    // f1 = relu(feat @ attn_W1 + b1): [46080 x 32 x 512]  (N=32 -> 64-wide kernel)
    {
        dim3 gf1(1, (NB * NG) / 64, 1);
        gemm64_kernel<false, 2><<<gf1, 256>>>(
            p_feat, NEF, 0, attn_W1, NAU, 0, attn_b1, 0,
            p_f1, NAU, 0, NB * NG, NAU, NEF);
    }

    for (int t = 0; t < NT; t++) {
        const float* a_in = p_aseq + (size_t)t * NB * NU;
        float* a_next     = p_aseq + (size_t)(t + 1) * NB * NU;
        attn_kernel<<<dim3(NB, 4), 512>>>(p_f1, p_feat, a_in, attn_W2, attn_b2,
                                          attn_V, attn_bV, p_x, attn_out, t);
        {   // serial gates split-K: 8 partials of [128 x 2048 x 128] (exact)
            dim3 gg(N4U / 128, NB / 128, NSK);
            gemm128_kernel<true, 0, true><<<gg, 256>>>(
                p_x, NKS, (size_t)NKSP,
                p_W, NKS, (size_t)NKSP,
                nullptr, 0,
                p_gp, N4U, (size_t)NB * N4U,
                NB, N4U, NKSP);
        }
        lstm_kernel<<<NB, 512>>>(p_gp, p_eg + (size_t)t * NB * N4U,
                                 a_next, p_c, ln_g, ln_b);
    }

    // ---- deferred decoder over all T*B rows (row r = t*NB + b) ----
    {   // d1 = leaky(aseq[1..T] @ dec_W1 + b1): [2560 x 256 x 512] (exact)
        dim3 gd1(256 / 128, (NT * NB) / 128, 1);
        gemm128_kernel<false, 1, true><<<gd1, 256>>>(
            p_aseq + (size_t)NB * NU, NU, 0, dec_W1, 256, 0, dec_b1, 0,
            p_d1, 256, 0, NT * NB, 256, NU);
    }
    {   // logits = d1 @ dec_W2 + b2: [2560 x 5000 x 256] (N guarded)
        dim3 gd2((NVOC + 127) / 128, (NT * NB) / 128, 1);
        gemm128_kernel<false, 0, false><<<gd2, 256>>>(
            p_d1, 256, 0, dec_W2, NVOC, 0, dec_b2, 0,
            p_lg, NVOC, 0, NT * NB, NVOC, 256);
    }
    vsm_kernel<<<NT * NB, 512>>>(p_lg, out);
}

// round 15
// speedup vs baseline: 1.9991x; 1.9991x over previous
#include <cuda_runtime.h>
#include <math.h>

#define NB   128
#define NG   360
#define NGI  174
#define NEF  512
#define NET  512
#define NU   512
#define NAU  32
#define NVOC 5000
#define NT   20
#define NKS  1024               // serial gates K: [ctx | a]
#define N4U  (4 * NU)           // 2048
#define NSK  16                 // split-K factor for serial gates GEMM
#define NKSP (NKS / NSK)        // 64

// ---------------- scratch (device globals; no allocation allowed) ----------------
__device__ float g_feat[(size_t)NB * NG * NEF];
__device__ float g_f1[(size_t)NB * NG * NAU];
__device__ float g_aseq[(size_t)(NT + 1) * NB * NU];
__device__ float g_c[2 * NB * NU];                 // double-buffered cell state
__device__ float g_xfull[NB * NKS];
__device__ float g_gpart[(size_t)NSK * NB * N4U];
__device__ float g_Wcat[(size_t)N4U * NKS];
__device__ float g_bsum[N4U];
__device__ float g_embseq[(size_t)NT * NB * NET];
__device__ float g_embg[(size_t)NT * NB * N4U];
__device__ float g_d1big[(size_t)NT * NB * 256];
__device__ float g_lgbig[(size_t)NT * NB * NVOC];

// ---------------- helpers ----------------
__device__ __forceinline__ float warpSum(float v) {
    #pragma unroll
    for (int o = 16; o; o >>= 1) v += __shfl_xor_sync(0xffffffffu, v, o);
    return v;
}
__device__ __forceinline__ float warpMax(float v) {
    #pragma unroll
    for (int o = 16; o; o >>= 1) v = fmaxf(v, __shfl_xor_sync(0xffffffffu, v, o));
    return v;
}
__device__ __forceinline__ float blockSum(float v, float* sm) {
    __syncthreads();
    int lane = threadIdx.x & 31, wid = threadIdx.x >> 5;
    v = warpSum(v);
    if (lane == 0) sm[wid] = v;
    __syncthreads();
    int nw = blockDim.x >> 5;
    float r = (threadIdx.x < nw) ? sm[threadIdx.x] : 0.f;
    if (wid == 0) { r = warpSum(r); if (lane == 0) sm[0] = r; }
    __syncthreads();
    return sm[0];
}
__device__ __forceinline__ float blockMax(float v, float* sm) {
    __syncthreads();
    int lane = threadIdx.x & 31, wid = threadIdx.x >> 5;
    v = warpMax(v);
    if (lane == 0) sm[wid] = v;
    __syncthreads();
    int nw = blockDim.x >> 5;
    float r = (threadIdx.x < nw) ? sm[threadIdx.x] : -INFINITY;
    if (wid == 0) { r = warpMax(r); if (lane == 0) sm[0] = r; }
    __syncthreads();
    return sm[0];
}
__device__ __forceinline__ float sigmoidf(float x) { return 1.f / (1.f + expf(-x)); }
__device__ __forceinline__ float leakyf(float x)  { return x >= 0.f ? x : 0.2f * x; }

// =================== 128x128-tile SGEMM, 8x8 microtile, K-chunk 8 (R12, scalar) ======
// Requires M % 128 == 0. EXACT=true: N%128==0, K%8==0 -> all guards removed.
// BT=true: B is [N,K] row-major; BT=false: B is [K,N].
template<bool BT, int EPI, bool EXACT>
__global__ void __launch_bounds__(256, 2) gemm128_kernel(
    const float* __restrict__ A, int lda, size_t aBatch,
    const float* __restrict__ Bm, int ldb, size_t bBatch,
    const float* __restrict__ bias, size_t biasBatch,
    float* __restrict__ C, int ldc, size_t cBatch,
    int M, int N, int K)
{
    __shared__ __align__(16) float As[2][8][132];
    __shared__ __align__(16) float Bs[2][8][132];
    A    += (size_t)blockIdx.z * aBatch;
    Bm   += (size_t)blockIdx.z * bBatch;
    if (bias) bias += (size_t)blockIdx.z * biasBatch;
    C    += (size_t)blockIdx.z * cBatch;

    const int n0 = blockIdx.x * 128;
    const int m0 = blockIdx.y * 128;
    const int tid = threadIdx.x;
    const int tx = tid & 15;
    const int ty = tid >> 4;

    const int amr = tid >> 1;
    const int akb = (tid & 1) << 2;
    const float* aPtr = A + (size_t)(m0 + amr) * lda + akb;
    const int bnr = tid >> 1;
    const int bkb = (tid & 1) << 2;
    const int bkr = tid >> 5;
    const int bnc = (tid & 31) << 2;
    const float* bPtr = BT ? (Bm + (size_t)(n0 + bnr) * ldb + bkb)
                           : (Bm + (size_t)bkr * ldb + n0 + bnc);
    const bool bok = EXACT || (BT ? (n0 + bnr) < N : (n0 + bnc + 4) <= N);

    float acc[8][8] = {};
    float aR[4], bR[4];
    const float4 z4 = make_float4(0.f, 0.f, 0.f, 0.f);
    const int nch = (K + 7) >> 3;

    if (EXACT) {
        float4 v = *(const float4*)aPtr;
        aR[0] = v.x; aR[1] = v.y; aR[2] = v.z; aR[3] = v.w;
    } else {
        #pragma unroll
        for (int j = 0; j < 4; j++) aR[j] = (akb + j < K) ? aPtr[j] : 0.f;
    }
    aPtr += 8;
    if (BT) {
        float4 v = (bok && (EXACT || bkb + 4 <= K)) ? *(const float4*)bPtr : z4;
        bR[0] = v.x; bR[1] = v.y; bR[2] = v.z; bR[3] = v.w;
        bPtr += 8;
    } else {
        float4 v = (bok && (EXACT || bkr < K)) ? *(const float4*)bPtr : z4;
        bR[0] = v.x; bR[1] = v.y; bR[2] = v.z; bR[3] = v.w;
        bPtr += (size_t)8 * ldb;
    }
    #pragma unroll
    for (int j = 0; j < 4; j++) As[0][akb + j][amr] = aR[j];
    if (BT) {
        #pragma unroll
        for (int j = 0; j < 4; j++) Bs[0][bkb + j][bnr] = bR[j];
    } else {
        *(float4*)&Bs[0][bkr][bnc] = make_float4(bR[0], bR[1], bR[2], bR[3]);
    }
    __syncthreads();

    for (int kc = 0; kc < nch; kc++) {
        const int cur = kc & 1, nxt = cur ^ 1;
        const bool more = (kc + 1) < nch;
        if (more) {
            const int k0 = (kc + 1) << 3;
            if (EXACT) {
                float4 v = *(const float4*)aPtr;
                aR[0] = v.x; aR[1] = v.y; aR[2] = v.z; aR[3] = v.w;
            } else {
                #pragma unroll
                for (int j = 0; j < 4; j++) aR[j] = (k0 + akb + j < K) ? aPtr[j] : 0.f;
            }
            aPtr += 8;
            if (BT) {
                float4 v = (bok && (EXACT || k0 + bkb + 4 <= K)) ? *(const float4*)bPtr : z4;
                bR[0] = v.x; bR[1] = v.y; bR[2] = v.z; bR[3] = v.w;
                bPtr += 8;
            } else {
                float4 v = (bok && (EXACT || k0 + bkr < K)) ? *(const float4*)bPtr : z4;
                bR[0] = v.x; bR[1] = v.y; bR[2] = v.z; bR[3] = v.w;
                bPtr += (size_t)8 * ldb;
            }
        }
        #pragma unroll
        for (int k = 0; k < 8; k++) {
            float4 a0 = *(const float4*)&As[cur][k][ty << 3];
            float4 a1 = *(const float4*)&As[cur][k][(ty << 3) + 4];
            float4 b0 = *(const float4*)&Bs[cur][k][tx << 2];
            float4 b1 = *(const float4*)&Bs[cur][k][64 + (tx << 2)];
            float av[8] = {a0.x, a0.y, a0.z, a0.w, a1.x, a1.y, a1.z, a1.w};
            float bv[8] = {b0.x, b0.y, b0.z, b0.w, b1.x, b1.y, b1.z, b1.w};
            #pragma unroll
            for (int i = 0; i < 8; i++) {
                #pragma unroll
                for (int j = 0; j < 8; j++) acc[i][j] += av[i] * bv[j];
            }
        }
        if (more) {
            #pragma unroll
            for (int j = 0; j < 4; j++) As[nxt][akb + j][amr] = aR[j];
            if (BT) {
                #pragma unroll
                for (int j = 0; j < 4; j++) Bs[nxt][bkb + j][bnr] = bR[j];
            } else {
                *(float4*)&Bs[nxt][bkr][bnc] = make_float4(bR[0], bR[1], bR[2], bR[3]);
            }
            __syncthreads();
        }
    }

    #pragma unroll
    for (int gEp = 0; gEp < 2; gEp++) {
        const int c = n0 + gEp * 64 + (tx << 2);
        const int jb = gEp * 4;
        if (EXACT || c + 4 <= N) {
            float bv0 = bias ? bias[c]     : 0.f;
            float bv1 = bias ? bias[c + 1] : 0.f;
            float bv2 = bias ? bias[c + 2] : 0.f;
            float bv3 = bias ? bias[c + 3] : 0.f;
            #pragma unroll
            for (int i = 0; i < 8; i++) {
                int m = m0 + (ty << 3) + i;
                float v0 = acc[i][jb]     + bv0;
                float v1 = acc[i][jb + 1] + bv1;
                float v2 = acc[i][jb + 2] + bv2;
                float v3 = acc[i][jb + 3] + bv3;
                if (EPI == 1) { v0 = leakyf(v0); v1 = leakyf(v1); v2 = leakyf(v2); v3 = leakyf(v3); }
                if (EPI == 2) { v0 = fmaxf(v0, 0.f); v1 = fmaxf(v1, 0.f); v2 = fmaxf(v2, 0.f); v3 = fmaxf(v3, 0.f); }
                *(float4*)&C[(size_t)m * ldc + c] = make_float4(v0, v1, v2, v3);
            }
        }
    }
}

// =================== specialized f1 kernel: [46080 x 32] = feat[46080 x 512] @ W1 ======
// 256-row x 32-col tile, 8x4 microtile, K-chunk 8, double-buffered. M % 256 == 0.
__global__ void __launch_bounds__(256, 2) f1_kernel(
    const float* __restrict__ feat, const float* __restrict__ W1,
    const float* __restrict__ b1, float* __restrict__ out)
{
    __shared__ __align__(16) float As[2][8][260];
    __shared__ __align__(16) float Bs[2][8][36];
    const int m0 = blockIdx.x * 256;
    const int tid = threadIdx.x;
    const int tx = tid & 7;    // cols tx*4 .. +3
    const int ty = tid >> 3;   // rows ty*8 .. +7
    const float* aPtr = feat + (size_t)(m0 + tid) * NEF;   // one row per thread
    const bool bload = tid < 64;
    const int bk = tid >> 3;        // 0..7 (valid when tid<64)
    const int bc = (tid & 7) << 2;  // 0..28

    float acc[8][4] = {};
    float4 aA, aB, bv;
    const int nch = NEF / 8;   // 64

    // prologue
    aA = *(const float4*)aPtr; aB = *(const float4*)(aPtr + 4); aPtr += 8;
    if (bload) bv = *(const float4*)&W1[(size_t)bk * NAU + bc];
    As[0][0][tid] = aA.x; As[0][1][tid] = aA.y; As[0][2][tid] = aA.z; As[0][3][tid] = aA.w;
    As[0][4][tid] = aB.x; As[0][5][tid] = aB.y; As[0][6][tid] = aB.z; As[0][7][tid] = aB.w;
    if (bload) *(float4*)&Bs[0][bk][bc] = bv;
    __syncthreads();

    for (int kc = 0; kc < nch; kc++) {
        const int cur = kc & 1, nxt = cur ^ 1;
        const bool more = (kc + 1) < nch;
        if (more) {
            aA = *(const float4*)aPtr; aB = *(const float4*)(aPtr + 4); aPtr += 8;
            if (bload) bv = *(const float4*)&W1[(size_t)((kc + 1) * 8 + bk) * NAU + bc];
        }
        #pragma unroll
        for (int k = 0; k < 8; k++) {
            float4 a0 = *(const float4*)&As[cur][k][ty << 3];
            float4 a1 = *(const float4*)&As[cur][k][(ty << 3) + 4];
            float4 b4 = *(const float4*)&Bs[cur][k][tx << 2];
            float av[8] = {a0.x, a0.y, a0.z, a0.w, a1.x, a1.y, a1.z, a1.w};
            #pragma unroll
            for (int i = 0; i < 8; i++) {
                acc[i][0] += av[i] * b4.x; acc[i][1] += av[i] * b4.y;
                acc[i][2] += av[i] * b4.z; acc[i][3] += av[i] * b4.w;
            }
        }
        if (more) {
            As[nxt][0][tid] = aA.x; As[nxt][1][tid] = aA.y; As[nxt][2][tid] = aA.z; As[nxt][3][tid] = aA.w;
            As[nxt][4][tid] = aB.x; As[nxt][5][tid] = aB.y; As[nxt][6][tid] = aB.z; As[nxt][7][tid] = aB.w;
            if (bload) *(float4*)&Bs[nxt][bk][bc] = bv;
            __syncthreads();
        }
    }

    const int c = tx << 2;
    float bb0 = b1[c], bb1 = b1[c + 1], bb2 = b1[c + 2], bb3 = b1[c + 3];
    #pragma unroll
    for (int i = 0; i < 8; i++) {
        int m = m0 + (ty << 3) + i;
        float v0 = fmaxf(acc[i][0] + bb0, 0.f);
        float v1 = fmaxf(acc[i][1] + bb1, 0.f);
        float v2 = fmaxf(acc[i][2] + bb2, 0.f);
        float v3 = fmaxf(acc[i][3] + bb3, 0.f);
        *(float4*)&out[(size_t)m * NAU + c] = make_float4(v0, v1, v2, v3);
    }
}

// ---------------- LayerNorm over rows of length 512 (in-place) ----------------
__global__ void __launch_bounds__(128) ln_rows_kernel(float* __restrict__ X,
    const float* __restrict__ gg, const float* __restrict__ bb)
{
    __shared__ float red[32];
    size_t row = blockIdx.x;
    float* xr = X + row * NEF;
    int tid = threadIdx.x;
    float v[4];
    #pragma unroll
    for (int j = 0; j < 4; j++) v[j] = xr[tid + 128 * j];
    float s = v[0] + v[1] + v[2] + v[3];
    float mean = blockSum(s, red) * (1.f / NEF);
    float sq = 0.f;
    #pragma unroll
    for (int j = 0; j < 4; j++) { float d = v[j] - mean; sq += d * d; }
    float var = blockSum(sq, red) * (1.f / NEF);
    float r = rsqrtf(var + 1e-5f);
    #pragma unroll
    for (int j = 0; j < 4; j++) {
        int cidx = tid + 128 * j;
        xr[cidx] = (v[j] - mean) * r * gg[cidx] + bb[cidx];
    }
}

// ---------------- pack [W_ih[:, :512] | W_hh] and b_ih + b_hh ----------------
__global__ void pack_kernel(const float* __restrict__ W_ih, const float* __restrict__ W_hh,
                            const float* __restrict__ b_ih, const float* __restrict__ b_hh)
{
    size_t idx = (size_t)blockIdx.x * blockDim.x + threadIdx.x;
    if (idx < (size_t)N4U * NKS) {
        int j = (int)(idx / NKS), k = (int)(idx % NKS);
        g_Wcat[idx] = (k < NEF) ? W_ih[(size_t)j * (NEF + NET) + k]
                                : W_hh[(size_t)j * NU + (k - NEF)];
    }
    if (idx < N4U) g_bsum[idx] = b_ih[idx] + b_hh[idx];
}

__global__ void init_kernel(const float* __restrict__ a0, const float* __restrict__ c0)
{
    int idx = blockIdx.x * blockDim.x + threadIdx.x;
    if (idx < NB * NU) { g_aseq[idx] = a0[idx]; g_c[idx] = c0[idx]; }   // cbuf[0] = c0
}

// ---------------- gather embedding rows: embseq[r = t*NB + b] = emb[text[b][t]] ----------
__global__ void gather_emb_kernel(const float* __restrict__ emb, const int* __restrict__ text)
{
    size_t idx = (size_t)blockIdx.x * blockDim.x + threadIdx.x;
    if (idx >= (size_t)NT * NB * NET) return;
    int r = (int)(idx >> 9);
    int col = (int)(idx & 511);
    int t = r / NB, b = r % NB;
    int tok = text[b * NT + t];
    g_embseq[idx] = emb[(size_t)tok * NET + col];
}

// ---------------- fused step kernel: [LSTM(t-1)] + h2 + scores + softmax + ctx + pack --
// grid (NB, 4). For t>0, every block recomputes LSTM(t-1) for its b from split-K
// partials (deterministic fp32 -> all chunks identical); chunk 0 writes aseq[t] and
// cout (double-buffered c, so concurrent blocks never read what chunk0 writes).
__global__ void __launch_bounds__(512) attn_kernel(
    const float* __restrict__ f1, const float* __restrict__ feat,
    const float* __restrict__ a0v,
    const float* __restrict__ gpart, const float* __restrict__ embg_prev,
    const float* __restrict__ cin, float* __restrict__ cout,
    const float* __restrict__ lng, const float* __restrict__ lnb,
    const float* __restrict__ W2, const float* __restrict__ b2,
    const float* __restrict__ V, const float* __restrict__ bV,
    float* __restrict__ xfull, float* __restrict__ attn_out,
    float* __restrict__ aseq_t, int t)
{
    int b = blockIdx.x, chunk = blockIdx.y, tid = threadIdx.x;
    __shared__ float a_s[NU];
    __shared__ float h2s[NAU];
    __shared__ float part[16][NAU];
    __shared__ float ss[NG];
    __shared__ float red[32];
    __shared__ float cpart[4][128];

    if (t == 0) {
        a_s[tid] = a0v[b * NU + tid];
    } else {
        // LSTM for step t-1 (identical arithmetic to the standalone lstm_kernel)
        int u = tid;
        const float* er = embg_prev + (size_t)b * N4U;
        float gi = er[u], gf = er[NU + u], gg = er[2 * NU + u], go = er[3 * NU + u];
        #pragma unroll
        for (int z = 0; z < NSK; z++) {
            const float* gr = gpart + (size_t)z * NB * N4U + (size_t)b * N4U;
            gi += gr[u]; gf += gr[NU + u]; gg += gr[2 * NU + u]; go += gr[3 * NU + u];
        }
        float cn = sigmoidf(gf) * cin[b * NU + u] + sigmoidf(gi) * tanhf(gg);
        float h  = sigmoidf(go) * tanhf(cn);
        if (chunk == 0) cout[b * NU + u] = cn;
        float hl = leakyf(h);
        float mean = blockSum(hl, red) * (1.f / NU);
        float d = hl - mean;
        float var = blockSum(d * d, red) * (1.f / NU);
        float r = rsqrtf(var + 1e-5f);
        float av = d * r * lng[u] + lnb[u];
        a_s[u] = av;
        if (chunk == 0) aseq_t[b * NU + u] = av;
    }
    __syncthreads();

    // h2 = relu(a @ W2 + b2), K=512 over 16 segments (a from smem)
    {
        int au = tid & 31, seg = tid >> 5;
        float acc = 0.f;
        #pragma unroll 8
        for (int kk = 0; kk < 32; kk++) {
            int k = seg * 32 + kk;
            acc += a_s[k] * W2[k * NAU + au];
        }
        part[seg][au] = acc;
    }
    __syncthreads();
    if (tid < NAU) {
        float s = 0.f;
        #pragma unroll
        for (int i = 0; i < 16; i++) s += part[i][tid];
        h2s[tid] = fmaxf(s + b2[tid], 0.f);
    }
    __syncthreads();

    // scores: one warp per group
    int wid = tid >> 5, lane = tid & 31;
    for (int g = wid; g < NG; g += 16) {
        float v = tanhf(f1[((size_t)b * NG + g) * NAU + lane] + h2s[lane]) * V[lane];
        v = warpSum(v);
        if (lane == 0) ss[g] = v + bV[0];
    }
    __syncthreads();

    // softmax over G=360
    float mx = -INFINITY;
    for (int g = tid; g < NG; g += 512) mx = fmaxf(mx, ss[g]);
    mx = blockMax(mx, red);
    float sum = 0.f;
    for (int g = tid; g < NG; g += 512) { float e = expf(ss[g] - mx); ss[g] = e; sum += e; }
    sum = blockSum(sum, red);
    float inv = 1.f / sum;
    for (int g = tid; g < NG; g += 512) {
        float w = ss[g] * inv;
        ss[g] = w;
        if (chunk == 0 && attn_out) attn_out[((size_t)b * NT + t) * NG + g] = w;
    }
    if (chunk == 0)
        xfull[(size_t)b * NKS + NEF + tid] = a_s[tid];
    __syncthreads();

    // ctx for this block's 128 ef-columns (4-way g-split + reduce)
    {
        int q = tid >> 7, e = tid & 127;
        int ef = chunk * 128 + e;
        const float* fb = feat + (size_t)b * NG * NEF + ef;
        float acc = 0.f;
        int g0 = q * 90;
        #pragma unroll 5
        for (int g = g0; g < g0 + 90; g++) acc += ss[g] * fb[(size_t)g * NEF];
        cpart[q][e] = acc;
    }
    __syncthreads();
    if (tid < 128) {
        float v = cpart[0][tid] + cpart[1][tid] + cpart[2][tid] + cpart[3][tid];
        xfull[(size_t)b * NKS + chunk * 128 + tid] = v;
    }
}

// ---------------- standalone LSTM (final step only) ----------------
__global__ void __launch_bounds__(512) lstm_kernel(
    const float* __restrict__ gpart, const float* __restrict__ embg_t,
    float* __restrict__ aout, const float* __restrict__ cin, float* __restrict__ cout,
    const float* __restrict__ lng, const float* __restrict__ lnb)
{
    __shared__ float red[32];
    int b = blockIdx.x, u = threadIdx.x;
    const float* er = embg_t + (size_t)b * N4U;
    float gi = er[u], gf = er[NU + u], gg = er[2 * NU + u], go = er[3 * NU + u];
    #pragma unroll
    for (int z = 0; z < NSK; z++) {
        const float* gr = gpart + (size_t)z * NB * N4U + (size_t)b * N4U;
        gi += gr[u]; gf += gr[NU + u]; gg += gr[2 * NU + u]; go += gr[3 * NU + u];
    }
    float cn = sigmoidf(gf) * cin[b * NU + u] + sigmoidf(gi) * tanhf(gg);
    float h  = sigmoidf(go) * tanhf(cn);
    cout[b * NU + u] = cn;
    float hl = leakyf(h);
    float mean = blockSum(hl, red) * (1.f / NU);
    float d = hl - mean;
    float var = blockSum(d * d, red) * (1.f / NU);
    float r = rsqrtf(var + 1e-5f);
    aout[b * NU + u] = d * r * lng[u] + lnb[u];
}

// ---------------- batched vocab softmax: rows r = t*NB + b -> out[b,t,:] ----------------
__global__ void __launch_bounds__(512) vsm_kernel(
    const float* __restrict__ logits, float* __restrict__ out)
{
    __shared__ float red[32];
    int r = blockIdx.x, tid = threadIdx.x;
    int t = r / NB, b = r % NB;
    const float* lr = logits + (size_t)r * NVOC;
    float* orow = out + ((size_t)b * NT + t) * NVOC;
    float mx = -INFINITY;
    for (int v = tid; v < NVOC; v += 512) mx = fmaxf(mx, lr[v]);
    mx = blockMax(mx, red);
    float s = 0.f;
    for (int v = tid; v < NVOC; v += 512) { float e = expf(lr[v] - mx); orow[v] = e; s += e; }
    s = blockSum(s, red);
    float inv = 1.f / s;
    for (int v = tid; v < NVOC; v += 512) orow[v] *= inv;
}

// ---------------- host ----------------
extern "C" void kernel_launch(void* const* d_in, const int* in_sizes, int n_in,
                              void* d_out, int out_size)
{
    const float* features = (const float*)d_in[0];
    const int*   text     = (const int*)  d_in[1];
    const float* a0       = (const float*)d_in[2];
    const float* c0       = (const float*)d_in[3];
    const float* enc_W    = (const float*)d_in[4];
    const float* enc_b    = (const float*)d_in[5];
    const float* enc_ln_g = (const float*)d_in[6];
    const float* enc_ln_b = (const float*)d_in[7];
    const float* attn_W1  = (const float*)d_in[8];
    const float* attn_b1  = (const float*)d_in[9];
    const float* attn_W2  = (const float*)d_in[10];
    const float* attn_b2  = (const float*)d_in[11];
    const float* attn_V   = (const float*)d_in[12];
    const float* attn_bV  = (const float*)d_in[13];
    const float* emb      = (const float*)d_in[14];
    const float* W_ih     = (const float*)d_in[15];
    const float* W_hh     = (const float*)d_in[16];
    const float* b_ih     = (const float*)d_in[17];
    const float* b_hh     = (const float*)d_in[18];
    const float* ln_g     = (const float*)d_in[19];
    const float* ln_b     = (const float*)d_in[20];
    const float* dec_W1   = (const float*)d_in[21];
    const float* dec_b1   = (const float*)d_in[22];
    const float* dec_W2   = (const float*)d_in[23];
    const float* dec_b2   = (const float*)d_in[24];

    float *p_feat, *p_f1, *p_aseq, *p_c, *p_x, *p_gp, *p_W, *p_bs, *p_es, *p_eg, *p_d1, *p_lg;
    cudaGetSymbolAddress((void**)&p_feat, g_feat);
    cudaGetSymbolAddress((void**)&p_f1,   g_f1);
    cudaGetSymbolAddress((void**)&p_aseq, g_aseq);
    cudaGetSymbolAddress((void**)&p_c,    g_c);
    cudaGetSymbolAddress((void**)&p_x,    g_xfull);
    cudaGetSymbolAddress((void**)&p_gp,   g_gpart);
    cudaGetSymbolAddress((void**)&p_W,    g_Wcat);
    cudaGetSymbolAddress((void**)&p_bs,   g_bsum);
    cudaGetSymbolAddress((void**)&p_es,   g_embseq);
    cudaGetSymbolAddress((void**)&p_eg,   g_embg);
    cudaGetSymbolAddress((void**)&p_d1,   g_d1big);
    cudaGetSymbolAddress((void**)&p_lg,   g_lgbig);

    float* out = (float*)d_out;
    float* attn_out = nullptr;
    long long need = (long long)NB * NT * NVOC + (long long)NB * NT * NG;
    if ((long long)out_size >= need) attn_out = out + (size_t)NB * NT * NVOC;

    pack_kernel<<<(int)(((size_t)N4U * NKS + 255) / 256), 256>>>(W_ih, W_hh, b_ih, b_hh);
    init_kernel<<<(NB * NU + 255) / 256, 256>>>(a0, c0);
    gather_emb_kernel<<<(int)(((size_t)NT * NB * NET + 255) / 256), 256>>>(emb, text);

    // embg = embseq @ W_ih[:, 512:1024]^T + (b_ih + b_hh): [2560 x 2048 x 512] (exact)
    {
        dim3 geg(N4U / 128, (NT * NB) / 128, 1);
        gemm128_kernel<true, 0, true><<<geg, 256>>>(
            p_es, NET, 0,
            W_ih + NEF, NEF + NET, 0,
            p_bs, 0,
            p_eg, N4U, 0,
            NT * NB, N4U, NET);
    }

    // encoder: per-group GEMM [128 x 512 x 174] + leaky, then LN (K guarded)
    {
        dim3 ge(NEF / 128, NB / 128, NG);
        gemm128_kernel<false, 1, false><<<ge, 256>>>(
            features, NG * NGI, (size_t)NGI,
            enc_W, NEF, (size_t)NGI * NEF,
            enc_b, (size_t)NEF,
            p_feat, NG * NEF, (size_t)NEF,
            NB, NEF, NGI);
        ln_rows_kernel<<<NB * NG, 128>>>(p_feat, enc_ln_g, enc_ln_b);
    }
    // f1 = relu(feat @ attn_W1 + b1): specialized 256x32 kernel
    f1_kernel<<<(NB * NG) / 256, 256>>>(p_feat, attn_W1, attn_b1, p_f1);

    // recurrence: attn(t) fuses LSTM(t-1); gates(t) produces partials for LSTM(t)
    for (int t = 0; t < NT; t++) {
        const float* cin = p_c + (size_t)((t + 1) & 1) * NB * NU;   // cbuf[(t-1)&1]
        float* cout      = p_c + (size_t)(t & 1) * NB * NU;         // cbuf[t&1]
        const float* eg_prev = (t > 0) ? (p_eg + (size_t)(t - 1) * NB * N4U) : p_eg;
        attn_kernel<<<dim3(NB, 4), 512>>>(
            p_f1, p_feat, p_aseq /* a0 */, p_gp, eg_prev, cin, cout,
            ln_g, ln_b, attn_W2, attn_b2, attn_V, attn_bV,
            p_x, attn_out, p_aseq + (size_t)t * NB * NU, t);
        {   // serial gates split-K: 16 partials of [128 x 2048 x 64] (exact)
            dim3 gg(N4U / 128, NB / 128, NSK);
            gemm128_kernel<true, 0, true><<<gg, 256>>>(
                p_x, NKS, (size_t)NKSP,
                p_W, NKS, (size_t)NKSP,
                nullptr, 0,
                p_gp, N4U, (size_t)NB * N4U,
                NB, N4U, NKSP);
        }
    }
    // final LSTM (step NT-1) -> aseq[NT]
    lstm_kernel<<<NB, 512>>>(p_gp, p_eg + (size_t)(NT - 1) * NB * N4U,
                             p_aseq + (size_t)NT * NB * NU,
                             p_c + (size_t)((NT - 1) & 1) * NB * NU,
                             p_c + (size_t)(NT & 1) * NB * NU,
                             ln_g, ln_b);

    // ---- deferred decoder over all T*B rows (row r = t*NB + b) ----
    {   // d1 = leaky(aseq[1..T] @ dec_W1 + b1): [2560 x 256 x 512] (exact)
        dim3 gd1(256 / 128, (NT * NB) / 128, 1);
        gemm128_kernel<false, 1, true><<<gd1, 256>>>(
            p_aseq + (size_t)NB * NU, NU, 0, dec_W1, 256, 0, dec_b1, 0,
            p_d1, 256, 0, NT * NB, 256, NU);
    }
    {   // logits = d1 @ dec_W2 + b2: [2560 x 5000 x 256] (N guarded)
        dim3 gd2((NVOC + 127) / 128, (NT * NB) / 128, 1);
        gemm128_kernel<false, 0, false><<<gd2, 256>>>(
            p_d1, 256, 0, dec_W2, NVOC, 0, dec_b2, 0,
            p_lg, NVOC, 0, NT * NB, NVOC, 256);
    }
    vsm_kernel<<<NT * NB, 512>>>(p_lg, out);
}

// round 16
// speedup vs baseline: 2.0254x; 1.0131x over previous
#include <cuda_runtime.h>
#include <math.h>

#define NB   128
#define NG   360
#define NGI  174
#define NEF  512
#define NET  512
#define NU   512
#define NAU  32
#define NVOC 5000
#define NT   20
#define NKS  1024               // serial gates K: [ctx | a]
#define N4U  (4 * NU)           // 2048
#define NSK  16                 // split-K factor for serial gates GEMM
#define NKSP (NKS / NSK)        // 64
#define DCH  5                  // decoder chunk size (steps)

// ---------------- scratch (device globals; no allocation allowed) ----------------
__device__ float g_feat[(size_t)NB * NG * NEF];
__device__ float g_f1[(size_t)NB * NG * NAU];
__device__ float g_aseq[(size_t)(NT + 1) * NB * NU];
__device__ float g_c[2 * NB * NU];                 // double-buffered cell state
__device__ float g_xfull[NB * NKS];
__device__ float g_gpart[(size_t)NSK * NB * N4U];
__device__ float g_Wcat[(size_t)N4U * NKS];
__device__ float g_bsum[N4U];
__device__ float g_embseq[(size_t)NT * NB * NET];
__device__ float g_embg[(size_t)NT * NB * N4U];
__device__ float g_d1big[(size_t)NT * NB * 256];
__device__ float g_lgbig[(size_t)NT * NB * NVOC];

// ---------------- helpers ----------------
__device__ __forceinline__ float warpSum(float v) {
    #pragma unroll
    for (int o = 16; o; o >>= 1) v += __shfl_xor_sync(0xffffffffu, v, o);
    return v;
}
__device__ __forceinline__ float warpMax(float v) {
    #pragma unroll
    for (int o = 16; o; o >>= 1) v = fmaxf(v, __shfl_xor_sync(0xffffffffu, v, o));
    return v;
}
__device__ __forceinline__ float blockSum(float v, float* sm) {
    __syncthreads();
    int lane = threadIdx.x & 31, wid = threadIdx.x >> 5;
    v = warpSum(v);
    if (lane == 0) sm[wid] = v;
    __syncthreads();
    int nw = blockDim.x >> 5;
    float r = (threadIdx.x < nw) ? sm[threadIdx.x] : 0.f;
    if (wid == 0) { r = warpSum(r); if (lane == 0) sm[0] = r; }
    __syncthreads();
    return sm[0];
}
__device__ __forceinline__ float blockMax(float v, float* sm) {
    __syncthreads();
    int lane = threadIdx.x & 31, wid = threadIdx.x >> 5;
    v = warpMax(v);
    if (lane == 0) sm[wid] = v;
    __syncthreads();
    int nw = blockDim.x >> 5;
    float r = (threadIdx.x < nw) ? sm[threadIdx.x] : -INFINITY;
    if (wid == 0) { r = warpMax(r); if (lane == 0) sm[0] = r; }
    __syncthreads();
    return sm[0];
}
__device__ __forceinline__ float sigmoidf(float x) { return 1.f / (1.f + expf(-x)); }
__device__ __forceinline__ float leakyf(float x)  { return x >= 0.f ? x : 0.2f * x; }

// =================== 128x128-tile SGEMM, 8x8 microtile, K-chunk 8 (R12, scalar) ======
// Requires M % 128 == 0. EXACT=true: N%128==0, K%8==0 -> all guards removed.
// BT=true: B is [N,K] row-major; BT=false: B is [K,N].
template<bool BT, int EPI, bool EXACT>
__global__ void __launch_bounds__(256, 2) gemm128_kernel(
    const float* __restrict__ A, int lda, size_t aBatch,
    const float* __restrict__ Bm, int ldb, size_t bBatch,
    const float* __restrict__ bias, size_t biasBatch,
    float* __restrict__ C, int ldc, size_t cBatch,
    int M, int N, int K)
{
    __shared__ __align__(16) float As[2][8][132];
    __shared__ __align__(16) float Bs[2][8][132];
    A    += (size_t)blockIdx.z * aBatch;
    Bm   += (size_t)blockIdx.z * bBatch;
    if (bias) bias += (size_t)blockIdx.z * biasBatch;
    C    += (size_t)blockIdx.z * cBatch;

    const int n0 = blockIdx.x * 128;
    const int m0 = blockIdx.y * 128;
    const int tid = threadIdx.x;
    const int tx = tid & 15;
    const int ty = tid >> 4;

    const int amr = tid >> 1;
    const int akb = (tid & 1) << 2;
    const float* aPtr = A + (size_t)(m0 + amr) * lda + akb;
    const int bnr = tid >> 1;
    const int bkb = (tid & 1) << 2;
    const int bkr = tid >> 5;
    const int bnc = (tid & 31) << 2;
    const float* bPtr = BT ? (Bm + (size_t)(n0 + bnr) * ldb + bkb)
                           : (Bm + (size_t)bkr * ldb + n0 + bnc);
    const bool bok = EXACT || (BT ? (n0 + bnr) < N : (n0 + bnc + 4) <= N);

    float acc[8][8] = {};
    float aR[4], bR[4];
    const float4 z4 = make_float4(0.f, 0.f, 0.f, 0.f);
    const int nch = (K + 7) >> 3;

    if (EXACT) {
        float4 v = *(const float4*)aPtr;
        aR[0] = v.x; aR[1] = v.y; aR[2] = v.z; aR[3] = v.w;
    } else {
        #pragma unroll
        for (int j = 0; j < 4; j++) aR[j] = (akb + j < K) ? aPtr[j] : 0.f;
    }
    aPtr += 8;
    if (BT) {
        float4 v = (bok && (EXACT || bkb + 4 <= K)) ? *(const float4*)bPtr : z4;
        bR[0] = v.x; bR[1] = v.y; bR[2] = v.z; bR[3] = v.w;
        bPtr += 8;
    } else {
        float4 v = (bok && (EXACT || bkr < K)) ? *(const float4*)bPtr : z4;
        bR[0] = v.x; bR[1] = v.y; bR[2] = v.z; bR[3] = v.w;
        bPtr += (size_t)8 * ldb;
    }
    #pragma unroll
    for (int j = 0; j < 4; j++) As[0][akb + j][amr] = aR[j];
    if (BT) {
        #pragma unroll
        for (int j = 0; j < 4; j++) Bs[0][bkb + j][bnr] = bR[j];
    } else {
        *(float4*)&Bs[0][bkr][bnc] = make_float4(bR[0], bR[1], bR[2], bR[3]);
    }
    __syncthreads();

    for (int kc = 0; kc < nch; kc++) {
        const int cur = kc & 1, nxt = cur ^ 1;
        const bool more = (kc + 1) < nch;
        if (more) {
            const int k0 = (kc + 1) << 3;
            if (EXACT) {
                float4 v = *(const float4*)aPtr;
                aR[0] = v.x; aR[1] = v.y; aR[2] = v.z; aR[3] = v.w;
            } else {
                #pragma unroll
                for (int j = 0; j < 4; j++) aR[j] = (k0 + akb + j < K) ? aPtr[j] : 0.f;
            }
            aPtr += 8;
            if (BT) {
                float4 v = (bok && (EXACT || k0 + bkb + 4 <= K)) ? *(const float4*)bPtr : z4;
                bR[0] = v.x; bR[1] = v.y; bR[2] = v.z; bR[3] = v.w;
                bPtr += 8;
            } else {
                float4 v = (bok && (EXACT || k0 + bkr < K)) ? *(const float4*)bPtr : z4;
                bR[0] = v.x; bR[1] = v.y; bR[2] = v.z; bR[3] = v.w;
                bPtr += (size_t)8 * ldb;
            }
        }
        #pragma unroll
        for (int k = 0; k < 8; k++) {
            float4 a0 = *(const float4*)&As[cur][k][ty << 3];
            float4 a1 = *(const float4*)&As[cur][k][(ty << 3) + 4];
            float4 b0 = *(const float4*)&Bs[cur][k][tx << 2];
            float4 b1 = *(const float4*)&Bs[cur][k][64 + (tx << 2)];
            float av[8] = {a0.x, a0.y, a0.z, a0.w, a1.x, a1.y, a1.z, a1.w};
            float bv[8] = {b0.x, b0.y, b0.z, b0.w, b1.x, b1.y, b1.z, b1.w};
            #pragma unroll
            for (int i = 0; i < 8; i++) {
                #pragma unroll
                for (int j = 0; j < 8; j++) acc[i][j] += av[i] * bv[j];
            }
        }
        if (more) {
            #pragma unroll
            for (int j = 0; j < 4; j++) As[nxt][akb + j][amr] = aR[j];
            if (BT) {
                #pragma unroll
                for (int j = 0; j < 4; j++) Bs[nxt][bkb + j][bnr] = bR[j];
            } else {
                *(float4*)&Bs[nxt][bkr][bnc] = make_float4(bR[0], bR[1], bR[2], bR[3]);
            }
            __syncthreads();
        }
    }

    #pragma unroll
    for (int gEp = 0; gEp < 2; gEp++) {
        const int c = n0 + gEp * 64 + (tx << 2);
        const int jb = gEp * 4;
        if (EXACT || c + 4 <= N) {
            float bv0 = bias ? bias[c]     : 0.f;
            float bv1 = bias ? bias[c + 1] : 0.f;
            float bv2 = bias ? bias[c + 2] : 0.f;
            float bv3 = bias ? bias[c + 3] : 0.f;
            #pragma unroll
            for (int i = 0; i < 8; i++) {
                int m = m0 + (ty << 3) + i;
                float v0 = acc[i][jb]     + bv0;
                float v1 = acc[i][jb + 1] + bv1;
                float v2 = acc[i][jb + 2] + bv2;
                float v3 = acc[i][jb + 3] + bv3;
                if (EPI == 1) { v0 = leakyf(v0); v1 = leakyf(v1); v2 = leakyf(v2); v3 = leakyf(v3); }
                if (EPI == 2) { v0 = fmaxf(v0, 0.f); v1 = fmaxf(v1, 0.f); v2 = fmaxf(v2, 0.f); v3 = fmaxf(v3, 0.f); }
                *(float4*)&C[(size_t)m * ldc + c] = make_float4(v0, v1, v2, v3);
            }
        }
    }
}

// =================== specialized f1 kernel: [46080 x 32] = feat @ W1 ==================
__global__ void __launch_bounds__(256, 2) f1_kernel(
    const float* __restrict__ feat, const float* __restrict__ W1,
    const float* __restrict__ b1, float* __restrict__ out)
{
    __shared__ __align__(16) float As[2][8][260];
    __shared__ __align__(16) float Bs[2][8][36];
    const int m0 = blockIdx.x * 256;
    const int tid = threadIdx.x;
    const int tx = tid & 7;
    const int ty = tid >> 3;
    const float* aPtr = feat + (size_t)(m0 + tid) * NEF;
    const bool bload = tid < 64;
    const int bk = tid >> 3;
    const int bc = (tid & 7) << 2;

    float acc[8][4] = {};
    float4 aA, aB, bv;
    const int nch = NEF / 8;

    aA = *(const float4*)aPtr; aB = *(const float4*)(aPtr + 4); aPtr += 8;
    if (bload) bv = *(const float4*)&W1[(size_t)bk * NAU + bc];
    As[0][0][tid] = aA.x; As[0][1][tid] = aA.y; As[0][2][tid] = aA.z; As[0][3][tid] = aA.w;
    As[0][4][tid] = aB.x; As[0][5][tid] = aB.y; As[0][6][tid] = aB.z; As[0][7][tid] = aB.w;
    if (bload) *(float4*)&Bs[0][bk][bc] = bv;
    __syncthreads();

    for (int kc = 0; kc < nch; kc++) {
        const int cur = kc & 1, nxt = cur ^ 1;
        const bool more = (kc + 1) < nch;
        if (more) {
            aA = *(const float4*)aPtr; aB = *(const float4*)(aPtr + 4); aPtr += 8;
            if (bload) bv = *(const float4*)&W1[(size_t)((kc + 1) * 8 + bk) * NAU + bc];
        }
        #pragma unroll
        for (int k = 0; k < 8; k++) {
            float4 a0 = *(const float4*)&As[cur][k][ty << 3];
            float4 a1 = *(const float4*)&As[cur][k][(ty << 3) + 4];
            float4 b4 = *(const float4*)&Bs[cur][k][tx << 2];
            float av[8] = {a0.x, a0.y, a0.z, a0.w, a1.x, a1.y, a1.z, a1.w};
            #pragma unroll
            for (int i = 0; i < 8; i++) {
                acc[i][0] += av[i] * b4.x; acc[i][1] += av[i] * b4.y;
                acc[i][2] += av[i] * b4.z; acc[i][3] += av[i] * b4.w;
            }
        }
        if (more) {
            As[nxt][0][tid] = aA.x; As[nxt][1][tid] = aA.y; As[nxt][2][tid] = aA.z; As[nxt][3][tid] = aA.w;
            As[nxt][4][tid] = aB.x; As[nxt][5][tid] = aB.y; As[nxt][6][tid] = aB.z; As[nxt][7][tid] = aB.w;
            if (bload) *(float4*)&Bs[nxt][bk][bc] = bv;
            __syncthreads();
        }
    }

    const int c = tx << 2;
    float bb0 = b1[c], bb1 = b1[c + 1], bb2 = b1[c + 2], bb3 = b1[c + 3];
    #pragma unroll
    for (int i = 0; i < 8; i++) {
        int m = m0 + (ty << 3) + i;
        float v0 = fmaxf(acc[i][0] + bb0, 0.f);
        float v1 = fmaxf(acc[i][1] + bb1, 0.f);
        float v2 = fmaxf(acc[i][2] + bb2, 0.f);
        float v3 = fmaxf(acc[i][3] + bb3, 0.f);
        *(float4*)&out[(size_t)m * NAU + c] = make_float4(v0, v1, v2, v3);
    }
}

// ---------------- LayerNorm over rows of length 512 (in-place) ----------------
__global__ void __launch_bounds__(128) ln_rows_kernel(float* __restrict__ X,
    const float* __restrict__ gg, const float* __restrict__ bb)
{
    __shared__ float red[32];
    size_t row = blockIdx.x;
    float* xr = X + row * NEF;
    int tid = threadIdx.x;
    float v[4];
    #pragma unroll
    for (int j = 0; j < 4; j++) v[j] = xr[tid + 128 * j];
    float s = v[0] + v[1] + v[2] + v[3];
    float mean = blockSum(s, red) * (1.f / NEF);
    float sq = 0.f;
    #pragma unroll
    for (int j = 0; j < 4; j++) { float d = v[j] - mean; sq += d * d; }
    float var = blockSum(sq, red) * (1.f / NEF);
    float r = rsqrtf(var + 1e-5f);
    #pragma unroll
    for (int j = 0; j < 4; j++) {
        int cidx = tid + 128 * j;
        xr[cidx] = (v[j] - mean) * r * gg[cidx] + bb[cidx];
    }
}

// ---------------- pack [W_ih[:, :512] | W_hh] and b_ih + b_hh ----------------
__global__ void pack_kernel(const float* __restrict__ W_ih, const float* __restrict__ W_hh,
                            const float* __restrict__ b_ih, const float* __restrict__ b_hh)
{
    size_t idx = (size_t)blockIdx.x * blockDim.x + threadIdx.x;
    if (idx < (size_t)N4U * NKS) {
        int j = (int)(idx / NKS), k = (int)(idx % NKS);
        g_Wcat[idx] = (k < NEF) ? W_ih[(size_t)j * (NEF + NET) + k]
                                : W_hh[(size_t)j * NU + (k - NEF)];
    }
    if (idx < N4U) g_bsum[idx] = b_ih[idx] + b_hh[idx];
}

__global__ void init_kernel(const float* __restrict__ a0, const float* __restrict__ c0)
{
    int idx = blockIdx.x * blockDim.x + threadIdx.x;
    if (idx < NB * NU) { g_aseq[idx] = a0[idx]; g_c[idx] = c0[idx]; }
}

// ---------------- gather embedding rows: embseq[r = t*NB + b] = emb[text[b][t]] ----------
__global__ void gather_emb_kernel(const float* __restrict__ emb, const int* __restrict__ text)
{
    size_t idx = (size_t)blockIdx.x * blockDim.x + threadIdx.x;
    if (idx >= (size_t)NT * NB * NET) return;
    int r = (int)(idx >> 9);
    int col = (int)(idx & 511);
    int t = r / NB, b = r % NB;
    int tok = text[b * NT + t];
    g_embseq[idx] = emb[(size_t)tok * NET + col];
}

// ---------------- fused step kernel: [LSTM(t-1)] + h2 + scores + softmax + ctx + pack --
__global__ void __launch_bounds__(512) attn_kernel(
    const float* __restrict__ f1, const float* __restrict__ feat,
    const float* __restrict__ a0v,
    const float* __restrict__ gpart, const float* __restrict__ embg_prev,
    const float* __restrict__ cin, float* __restrict__ cout,
    const float* __restrict__ lng, const float* __restrict__ lnb,
    const float* __restrict__ W2, const float* __restrict__ b2,
    const float* __restrict__ V, const float* __restrict__ bV,
    float* __restrict__ xfull, float* __restrict__ attn_out,
    float* __restrict__ aseq_t, int t)
{
    int b = blockIdx.x, chunk = blockIdx.y, tid = threadIdx.x;
    __shared__ float a_s[NU];
    __shared__ float h2s[NAU];
    __shared__ float part[16][NAU];
    __shared__ float ss[NG];
    __shared__ float red[32];
    __shared__ float cpart[4][128];

    if (t == 0) {
        a_s[tid] = a0v[b * NU + tid];
    } else {
        int u = tid;
        const float* er = embg_prev + (size_t)b * N4U;
        float gi = er[u], gf = er[NU + u], gg = er[2 * NU + u], go = er[3 * NU + u];
        #pragma unroll
        for (int z = 0; z < NSK; z++) {
            const float* gr = gpart + (size_t)z * NB * N4U + (size_t)b * N4U;
            gi += gr[u]; gf += gr[NU + u]; gg += gr[2 * NU + u]; go += gr[3 * NU + u];
        }
        float cn = sigmoidf(gf) * cin[b * NU + u] + sigmoidf(gi) * tanhf(gg);
        float h  = sigmoidf(go) * tanhf(cn);
        if (chunk == 0) cout[b * NU + u] = cn;
        float hl = leakyf(h);
        float mean = blockSum(hl, red) * (1.f / NU);
        float d = hl - mean;
        float var = blockSum(d * d, red) * (1.f / NU);
        float r = rsqrtf(var + 1e-5f);
        float av = d * r * lng[u] + lnb[u];
        a_s[u] = av;
        if (chunk == 0) aseq_t[b * NU + u] = av;
    }
    __syncthreads();

    {
        int au = tid & 31, seg = tid >> 5;
        float acc = 0.f;
        #pragma unroll 8
        for (int kk = 0; kk < 32; kk++) {
            int k = seg * 32 + kk;
            acc += a_s[k] * W2[k * NAU + au];
        }
        part[seg][au] = acc;
    }
    __syncthreads();
    if (tid < NAU) {
        float s = 0.f;
        #pragma unroll
        for (int i = 0; i < 16; i++) s += part[i][tid];
        h2s[tid] = fmaxf(s + b2[tid], 0.f);
    }
    __syncthreads();

    int wid = tid >> 5, lane = tid & 31;
    for (int g = wid; g < NG; g += 16) {
        float v = tanhf(f1[((size_t)b * NG + g) * NAU + lane] + h2s[lane]) * V[lane];
        v = warpSum(v);
        if (lane == 0) ss[g] = v + bV[0];
    }
    __syncthreads();

    float mx = -INFINITY;
    for (int g = tid; g < NG; g += 512) mx = fmaxf(mx, ss[g]);
    mx = blockMax(mx, red);
    float sum = 0.f;
    for (int g = tid; g < NG; g += 512) { float e = expf(ss[g] - mx); ss[g] = e; sum += e; }
    sum = blockSum(sum, red);
    float inv = 1.f / sum;
    for (int g = tid; g < NG; g += 512) {
        float w = ss[g] * inv;
        ss[g] = w;
        if (chunk == 0 && attn_out) attn_out[((size_t)b * NT + t) * NG + g] = w;
    }
    if (chunk == 0)
        xfull[(size_t)b * NKS + NEF + tid] = a_s[tid];
    __syncthreads();

    {
        int q = tid >> 7, e = tid & 127;
        int ef = chunk * 128 + e;
        const float* fb = feat + (size_t)b * NG * NEF + ef;
        float acc = 0.f;
        int g0 = q * 90;
        #pragma unroll 5
        for (int g = g0; g < g0 + 90; g++) acc += ss[g] * fb[(size_t)g * NEF];
        cpart[q][e] = acc;
    }
    __syncthreads();
    if (tid < 128) {
        float v = cpart[0][tid] + cpart[1][tid] + cpart[2][tid] + cpart[3][tid];
        xfull[(size_t)b * NKS + chunk * 128 + tid] = v;
    }
}

// ---------------- standalone LSTM (final step only) ----------------
__global__ void __launch_bounds__(512) lstm_kernel(
    const float* __restrict__ gpart, const float* __restrict__ embg_t,
    float* __restrict__ aout, const float* __restrict__ cin, float* __restrict__ cout,
    const float* __restrict__ lng, const float* __restrict__ lnb)
{
    __shared__ float red[32];
    int b = blockIdx.x, u = threadIdx.x;
    const float* er = embg_t + (size_t)b * N4U;
    float gi = er[u], gf = er[NU + u], gg = er[2 * NU + u], go = er[3 * NU + u];
    #pragma unroll
    for (int z = 0; z < NSK; z++) {
        const float* gr = gpart + (size_t)z * NB * N4U + (size_t)b * N4U;
        gi += gr[u]; gf += gr[NU + u]; gg += gr[2 * NU + u]; go += gr[3 * NU + u];
    }
    float cn = sigmoidf(gf) * cin[b * NU + u] + sigmoidf(gi) * tanhf(gg);
    float h  = sigmoidf(go) * tanhf(cn);
    cout[b * NU + u] = cn;
    float hl = leakyf(h);
    float mean = blockSum(hl, red) * (1.f / NU);
    float d = hl - mean;
    float var = blockSum(d * d, red) * (1.f / NU);
    float r = rsqrtf(var + 1e-5f);
    aout[b * NU + u] = d * r * lng[u] + lnb[u];
}

// ---------------- batched vocab softmax with row offset: r = r0 + blockIdx.x ----------
__global__ void __launch_bounds__(512) vsm_kernel(
    const float* __restrict__ logits, float* __restrict__ out, int r0)
{
    __shared__ float red[32];
    int r = r0 + blockIdx.x, tid = threadIdx.x;
    int t = r / NB, b = r % NB;
    const float* lr = logits + (size_t)r * NVOC;
    float* orow = out + ((size_t)b * NT + t) * NVOC;
    float mx = -INFINITY;
    for (int v = tid; v < NVOC; v += 512) mx = fmaxf(mx, lr[v]);
    mx = blockMax(mx, red);
    float s = 0.f;
    for (int v = tid; v < NVOC; v += 512) { float e = expf(lr[v] - mx); orow[v] = e; s += e; }
    s = blockSum(s, red);
    float inv = 1.f / s;
    for (int v = tid; v < NVOC; v += 512) orow[v] *= inv;
}

// ---------------- host ----------------
extern "C" void kernel_launch(void* const* d_in, const int* in_sizes, int n_in,
                              void* d_out, int out_size)
{
    const float* features = (const float*)d_in[0];
    const int*   text     = (const int*)  d_in[1];
    const float* a0       = (const float*)d_in[2];
    const float* c0       = (const float*)d_in[3];
    const float* enc_W    = (const float*)d_in[4];
    const float* enc_b    = (const float*)d_in[5];
    const float* enc_ln_g = (const float*)d_in[6];
    const float* enc_ln_b = (const float*)d_in[7];
    const float* attn_W1  = (const float*)d_in[8];
    const float* attn_b1  = (const float*)d_in[9];
    const float* attn_W2  = (const float*)d_in[10];
    const float* attn_b2  = (const float*)d_in[11];
    const float* attn_V   = (const float*)d_in[12];
    const float* attn_bV  = (const float*)d_in[13];
    const float* emb      = (const float*)d_in[14];
    const float* W_ih     = (const float*)d_in[15];
    const float* W_hh     = (const float*)d_in[16];
    const float* b_ih     = (const float*)d_in[17];
    const float* b_hh     = (const float*)d_in[18];
    const float* ln_g     = (const float*)d_in[19];
    const float* ln_b     = (const float*)d_in[20];
    const float* dec_W1   = (const float*)d_in[21];
    const float* dec_b1   = (const float*)d_in[22];
    const float* dec_W2   = (const float*)d_in[23];
    const float* dec_b2   = (const float*)d_in[24];

    float *p_feat, *p_f1, *p_aseq, *p_c, *p_x, *p_gp, *p_W, *p_bs, *p_es, *p_eg, *p_d1, *p_lg;
    cudaGetSymbolAddress((void**)&p_feat, g_feat);
    cudaGetSymbolAddress((void**)&p_f1,   g_f1);
    cudaGetSymbolAddress((void**)&p_aseq, g_aseq);
    cudaGetSymbolAddress((void**)&p_c,    g_c);
    cudaGetSymbolAddress((void**)&p_x,    g_xfull);
    cudaGetSymbolAddress((void**)&p_gp,   g_gpart);
    cudaGetSymbolAddress((void**)&p_W,    g_Wcat);
    cudaGetSymbolAddress((void**)&p_bs,   g_bsum);
    cudaGetSymbolAddress((void**)&p_es,   g_embseq);
    cudaGetSymbolAddress((void**)&p_eg,   g_embg);
    cudaGetSymbolAddress((void**)&p_d1,   g_d1big);
    cudaGetSymbolAddress((void**)&p_lg,   g_lgbig);

    float* out = (float*)d_out;
    float* attn_out = nullptr;
    long long need = (long long)NB * NT * NVOC + (long long)NB * NT * NG;
    if ((long long)out_size >= need) attn_out = out + (size_t)NB * NT * NVOC;

    // ---- one-time stream/event setup (first call is NOT under capture) ----
    static cudaStream_t s2 = nullptr;
    static cudaEvent_t evFork = nullptr, evPre = nullptr, evA[4] = {}, evDone = nullptr;
    if (s2 == nullptr) {
        cudaStreamCreateWithFlags(&s2, cudaStreamNonBlocking);
        cudaEventCreateWithFlags(&evFork, cudaEventDisableTiming);
        cudaEventCreateWithFlags(&evPre,  cudaEventDisableTiming);
        for (int i = 0; i < 4; i++) cudaEventCreateWithFlags(&evA[i], cudaEventDisableTiming);
        cudaEventCreateWithFlags(&evDone, cudaEventDisableTiming);
    }
    cudaStream_t s0 = 0;  // default (capture origin) stream

    // decoder chunk launcher: steps [t0, t0+DCH) on stream s2
    auto launch_dec_chunk = [&](int t0) {
        const int rows = DCH * NB;                       // 640
        const float* ain = p_aseq + (size_t)(t0 + 1) * NB * NU;
        float* d1c = p_d1 + (size_t)t0 * NB * 256;
        float* lgc = p_lg + (size_t)t0 * NB * NVOC;
        dim3 gd1(256 / 128, rows / 128, 1);
        gemm128_kernel<false, 1, true><<<gd1, 256, 0, s2>>>(
            ain, NU, 0, dec_W1, 256, 0, dec_b1, 0,
            d1c, 256, 0, rows, 256, NU);
        dim3 gd2((NVOC + 127) / 128, rows / 128, 1);
        gemm128_kernel<false, 0, false><<<gd2, 256, 0, s2>>>(
            d1c, 256, 0, dec_W2, NVOC, 0, dec_b2, 0,
            lgc, NVOC, 0, rows, NVOC, 256);
        vsm_kernel<<<rows, 512, 0, s2>>>(p_lg, out, t0 * NB);
    };

    // ---- fork stream2: prologue (pack -> gather -> embg) ----
    cudaEventRecord(evFork, s0);
    cudaStreamWaitEvent(s2, evFork, 0);
    pack_kernel<<<(int)(((size_t)N4U * NKS + 255) / 256), 256, 0, s2>>>(W_ih, W_hh, b_ih, b_hh);
    gather_emb_kernel<<<(int)(((size_t)NT * NB * NET + 255) / 256), 256, 0, s2>>>(emb, text);
    {
        dim3 geg(N4U / 128, (NT * NB) / 128, 1);
        gemm128_kernel<true, 0, true><<<geg, 256, 0, s2>>>(
            p_es, NET, 0,
            W_ih + NEF, NEF + NET, 0,
            p_bs, 0,
            p_eg, N4U, 0,
            NT * NB, N4U, NET);
    }
    cudaEventRecord(evPre, s2);

    // ---- main stream: encoder path ----
    init_kernel<<<(NB * NU + 255) / 256, 256, 0, s0>>>(a0, c0);
    {
        dim3 ge(NEF / 128, NB / 128, NG);
        gemm128_kernel<false, 1, false><<<ge, 256, 0, s0>>>(
            features, NG * NGI, (size_t)NGI,
            enc_W, NEF, (size_t)NGI * NEF,
            enc_b, (size_t)NEF,
            p_feat, NG * NEF, (size_t)NEF,
            NB, NEF, NGI);
        ln_rows_kernel<<<NB * NG, 128, 0, s0>>>(p_feat, enc_ln_g, enc_ln_b);
    }
    f1_kernel<<<(NB * NG) / 256, 256, 0, s0>>>(p_feat, attn_W1, attn_b1, p_f1);

    // ---- recurrence; decoder chunks pipelined on s2 ----
    for (int t = 0; t < NT; t++) {
        const float* cin = p_c + (size_t)((t + 1) & 1) * NB * NU;
        float* cout      = p_c + (size_t)(t & 1) * NB * NU;
        const float* eg_prev = (t > 0) ? (p_eg + (size_t)(t - 1) * NB * N4U) : p_eg;
        attn_kernel<<<dim3(NB, 4), 512, 0, s0>>>(
            p_f1, p_feat, p_aseq /* a0 */, p_gp, eg_prev, cin, cout,
            ln_g, ln_b, attn_W2, attn_b2, attn_V, attn_bV,
            p_x, attn_out, p_aseq + (size_t)t * NB * NU, t);
        // decoder chunk k ready after attn((k+1)*DCH) wrote aseq[k*DCH+1 .. k*DCH+DCH]
        if (t == DCH || t == 2 * DCH || t == 3 * DCH) {
            int k = t / DCH - 1;
            cudaEventRecord(evA[k], s0);
            cudaStreamWaitEvent(s2, evA[k], 0);
            launch_dec_chunk(k * DCH);
        }
        if (t == 0) cudaStreamWaitEvent(s0, evPre, 0);   // gates needs Wcat/embg path
        {   // serial gates split-K: 16 partials of [128 x 2048 x 64] (exact)
            dim3 gg(N4U / 128, NB / 128, NSK);
            gemm128_kernel<true, 0, true><<<gg, 256, 0, s0>>>(
                p_x, NKS, (size_t)NKSP,
                p_W, NKS, (size_t)NKSP,
                nullptr, 0,
                p_gp, N4U, (size_t)NB * N4U,
                NB, N4U, NKSP);
        }
    }
    // final LSTM (step NT-1) -> aseq[NT]
    lstm_kernel<<<NB, 512, 0, s0>>>(p_gp, p_eg + (size_t)(NT - 1) * NB * N4U,
                                    p_aseq + (size_t)NT * NB * NU,
                                    p_c + (size_t)((NT - 1) & 1) * NB * NU,
                                    p_c + (size_t)(NT & 1) * NB * NU,
                                    ln_g, ln_b);
    // last decoder chunk (steps 15..19) after final lstm
    cudaEventRecord(evA[3], s0);
    cudaStreamWaitEvent(s2, evA[3], 0);
    launch_dec_chunk(3 * DCH);

    // ---- join stream2 back into the origin stream ----
    cudaEventRecord(evDone, s2);
    cudaStreamWaitEvent(s0, evDone, 0);
}